// round 13
// baseline (speedup 1.0000x reference)
#include <cuda_runtime.h>
#include <cstdint>

// Problem shape (fixed for this instance)
#define NUM_SP 2048
#define CCH    64
#define NPIX   (1024 * 1024)

// Accum half-kernel tile: 128 px x 32 ch per block
#define A_PX   128
#define A_BLOCKS (NPIX / A_PX)             // 8192

// Gather tiling: 16384 px per (cg, chunk) tile, 64 chunks, 8 cgs per half
#define QITER  16
#define PIX_PER_TILE (QITER * 256 * 4)     // 16384
#define N_CHUNKS (NPIX / PIX_PER_TILE)     // 64
#define G_BLOCKS (N_CHUNKS * 8)            // 512 per half

// AG fused kernel: every 17th block gathers -> 8704 = 512 + 8192 exactly
#define AG_BLOCKS (A_BLOCKS + G_BLOCKS)    // 8704

// Scratch (allocation-free rule: __device__ globals)
__device__ float g_sums[NUM_SP * CCH];   // [S, C] row-major, 512 KB (L2-hot)
__device__ float g_cnt[NUM_SP];

// -------------------------------------------------------------------------
// Kernel 1: zero scratch (vectorized)
// -------------------------------------------------------------------------
__global__ void zero_kernel() {
    int i = blockIdx.x * blockDim.x + threadIdx.x;
    reinterpret_cast<float4*>(g_sums)[i] = make_float4(0.f, 0.f, 0.f, 0.f);
    if (i < NUM_SP / 4)
        reinterpret_cast<float4*>(g_cnt)[i] = make_float4(0.f, 0.f, 0.f, 0.f);
}

// Profiling alignment shim: order noop, zero, A0, AG -> ncu slot #4 = AG.
__global__ void noop_kernel() {}

// -------------------------------------------------------------------------
// Vectorized fire-and-forget global reduction (no "memory" clobber).
// -------------------------------------------------------------------------
__device__ __forceinline__ void red_add_v4(float* addr, float a, float b,
                                           float c, float d) {
    asm volatile("red.global.add.v4.f32 [%0], {%1, %2, %3, %4};"
                 :: "l"(addr), "f"(a), "f"(b), "f"(c), "f"(d));
}

// -------------------------------------------------------------------------
// Shared building blocks
// -------------------------------------------------------------------------
struct AccumSmem {
    float4 t[A_PX * 8];      // 16 KB, swizzled [px][c4]
    int    seg[A_PX];
};
union SmemU {
    AccumSmem a;
    float4 means[NUM_SP];    // 32 KB
};

// Accum body: 128 px x 32 ch starting at channel cbase, pixel base p0.
// Proven 40us/half body from R12: coalesced streaming LDG.128, swizzled
// scalar-STS transpose, line-coalesced RED.v4 (lanes 0-7 = 8 cgs of one px).
__device__ __forceinline__ void accum_body(
    AccumSmem& sm, const float* __restrict__ x, const int* __restrict__ sp,
    int cbase, int p0, int t, bool do_counts) {
    if (t < A_PX / 4) {
        int4 v = reinterpret_cast<const int4*>(sp + p0)[t];
        sm.seg[t * 4 + 0] = v.x;
        sm.seg[t * 4 + 1] = v.y;
        sm.seg[t * 4 + 2] = v.z;
        sm.seg[t * 4 + 3] = v.w;
    }

    float* s_f = reinterpret_cast<float*>(sm.t);
#pragma unroll
    for (int i = 0; i < 4; i++) {
        int idx = i * 256 + t;            // 0..1023
        int c   = idx >> 5;               // local channel 0..31
        int f   = idx & 31;               // float4 column 0..31
        float4 v = __ldcs(reinterpret_cast<const float4*>(
            x + (size_t)(cbase + c) * NPIX + p0 + f * 4));
        int c4 = c >> 2, comp = c & 3;
#pragma unroll
        for (int k = 0; k < 4; k++) {
            int px   = f * 4 + k;
            int slot = px * 8 + (c4 ^ (f & 7));   // f == px>>2
            s_f[slot * 4 + comp] = (&v.x)[k];
        }
    }
    __syncthreads();

    if (do_counts && t < A_PX) atomicAdd(&g_cnt[sm.seg[t]], 1.0f);

#pragma unroll
    for (int r = 0; r < 4; r++) {
        int pair = r * 256 + t;           // 0..1023
        int px   = pair >> 3;             // lanes 0-7 same px
        int cg   = pair & 7;
        int seg  = sm.seg[px];
        float4 v = sm.t[px * 8 + (cg ^ ((px >> 2) & 7))];
        red_add_v4(&g_sums[(size_t)seg * CCH + cbase + cg * 4],
                   v.x, v.y, v.z, v.w);
    }
}

__device__ __forceinline__ void stage_means(float4* s_means, int cg, int tid) {
#pragma unroll
    for (int i = 0; i < NUM_SP / 256; i++) {
        int s = i * 256 + tid;
        float4 sum = *reinterpret_cast<const float4*>(
            &g_sums[(size_t)s * CCH + cg * 4]);
        float inv = __frcp_rn(fmaxf(g_cnt[s], 1.0f));
        s_means[s] = make_float4(sum.x * inv, sum.y * inv,
                                 sum.z * inv, sum.w * inv);
    }
}

__device__ __forceinline__ void gather_chunk(
    const int* __restrict__ sp, float* __restrict__ out,
    const float4* s_means, int cg, int pixBase, int tid) {
#pragma unroll
    for (int q = 0; q < QITER; q++) {
        int p = pixBase + (q * 256 + tid) * 4;
        int4 s4 = *reinterpret_cast<const int4*>(sp + p);

        float4 a = s_means[s4.x];
        float4 b = s_means[s4.y];
        float4 c = s_means[s4.z];
        float4 d = s_means[s4.w];

        __stcs(reinterpret_cast<float4*>(out + (size_t)(cg * 4 + 0) * NPIX + p),
               make_float4(a.x, b.x, c.x, d.x));
        __stcs(reinterpret_cast<float4*>(out + (size_t)(cg * 4 + 1) * NPIX + p),
               make_float4(a.y, b.y, c.y, d.y));
        __stcs(reinterpret_cast<float4*>(out + (size_t)(cg * 4 + 2) * NPIX + p),
               make_float4(a.z, b.z, c.z, d.z));
        __stcs(reinterpret_cast<float4*>(out + (size_t)(cg * 4 + 3) * NPIX + p),
               make_float4(a.w, b.w, c.w, d.w));
    }
}

// -------------------------------------------------------------------------
// Kernel 2: A0 — accumulate channels 0-31 + counts (runs alone).
// -------------------------------------------------------------------------
__global__ void __launch_bounds__(256) a0_kernel(
    const float* __restrict__ x, const int* __restrict__ sp) {
    __shared__ AccumSmem sm;
    accum_body(sm, x, sp, /*cbase=*/0, blockIdx.x * A_PX, threadIdx.x,
               /*do_counts=*/true);
}

// -------------------------------------------------------------------------
// Kernel 3: AG — FUSED overlap kernel.
// Every 17th block (bx % 17 == 0; exactly 512 of 8704) gathers channels
// 0-31 (sums+counts complete: A0 preceded in-stream). The other 8192
// blocks accumulate channels 32-63 (independent of gather's data).
// The atomic-ALU-bound accum traffic and the DRAM-write-bound gather
// traffic use different hardware, so they co-run on the same SMs.
// -------------------------------------------------------------------------
__global__ void __launch_bounds__(256) ag_kernel(
    const float* __restrict__ x, const int* __restrict__ sp,
    float* __restrict__ out) {
    __shared__ SmemU u;
    int bx  = blockIdx.x;
    int tid = threadIdx.x;

    if (bx % 17 == 0) {
        int g     = bx / 17;          // 0..511
        int cg    = g & 7;            // channel group 0..7 (ch 0-31)
        int chunk = g >> 3;           // 0..63
        stage_means(u.means, cg, tid);
        __syncthreads();
        gather_chunk(sp, out, u.means, cg, chunk * PIX_PER_TILE, tid);
    } else {
        int ab = bx - bx / 17 - 1;    // accum block 0..8191 (bijective)
        accum_body(u.a, x, sp, /*cbase=*/32, ab * A_PX, tid,
                   /*do_counts=*/false);
    }
}

// -------------------------------------------------------------------------
// Kernel 4: G1 — gather channels 32-63 (cg 8..15) after AG completes.
// -------------------------------------------------------------------------
__global__ void __launch_bounds__(256) g1_kernel(
    const int* __restrict__ sp, float* __restrict__ out) {
    __shared__ float4 s_means[NUM_SP];
    int tid = threadIdx.x;
    int cg  = 8 + blockIdx.y;

    stage_means(s_means, cg, tid);
    __syncthreads();
    gather_chunk(sp, out, s_means, cg, blockIdx.x * PIX_PER_TILE, tid);
}

// -------------------------------------------------------------------------
// kernel_launch: graph-capturable, plain stream ordering (PDL removed —
// proven ineffective in-graph). Order: noop, zero, A0, AG, G1.
// ncu capture slot #4 = AG (the fused overlap kernel).
// -------------------------------------------------------------------------
extern "C" void kernel_launch(void* const* d_in, const int* in_sizes, int n_in,
                              void* d_out, int out_size) {
    const float* x  = (const float*)d_in[0];
    const int*   sp = (const int*)d_in[1];
    float*       out = (float*)d_out;

    const int threads = 256;
    const int zero_blocks = (NUM_SP * CCH / 4) / threads;   // 128

    noop_kernel<<<1, 1>>>();
    zero_kernel<<<zero_blocks, threads>>>();
    a0_kernel<<<A_BLOCKS, threads>>>(x, sp);
    ag_kernel<<<AG_BLOCKS, threads>>>(x, sp, out);
    g1_kernel<<<dim3(N_CHUNKS, 8), threads>>>(sp, out);
}

// round 14
// speedup vs baseline: 1.0392x; 1.0392x over previous
#include <cuda_runtime.h>
#include <cstdint>

// Problem shape (fixed for this instance)
#define NUM_SP 2048
#define CCH    64
#define NPIX   (1024 * 1024)

// Accum half-kernel tile: 128 px x 32 ch per block (measured 40us/half)
#define A_PX   128
#define A_BLOCKS (NPIX / A_PX)             // 8192

// Gather tiling: 16384 px per (cg, chunk) tile, 64 chunks, 8 cgs per half
#define QITER  16
#define PIX_PER_TILE (QITER * 256 * 4)     // 16384
#define N_CHUNKS (NPIX / PIX_PER_TILE)     // 64

// Scratch (allocation-free rule: __device__ globals)
__device__ float g_sums[NUM_SP * CCH];   // [S, C] row-major, 512 KB (L2-hot)
__device__ float g_cnt[NUM_SP];

// -------------------------------------------------------------------------
// Kernel 1: zero scratch (vectorized)
// -------------------------------------------------------------------------
__global__ void zero_kernel() {
    int i = blockIdx.x * blockDim.x + threadIdx.x;
    reinterpret_cast<float4*>(g_sums)[i] = make_float4(0.f, 0.f, 0.f, 0.f);
    if (i < NUM_SP / 4)
        reinterpret_cast<float4*>(g_cnt)[i] = make_float4(0.f, 0.f, 0.f, 0.f);
}

// -------------------------------------------------------------------------
// Vectorized fire-and-forget global reduction (no "memory" clobber).
// -------------------------------------------------------------------------
__device__ __forceinline__ void red_add_v4(float* addr, float a, float b,
                                           float c, float d) {
    asm volatile("red.global.add.v4.f32 [%0], {%1, %2, %3, %4};"
                 :: "l"(addr), "f"(a), "f"(b), "f"(c), "f"(d));
}

// -------------------------------------------------------------------------
// Kernel 2: accumulate channels [cbase, cbase+32) — measured 40us/half.
// Tile = 128 px x 32 ch, regs 32:
//   phase 1: coalesced streaming LDG.128, scalar-STS into swizzled
//            s_t[px][c4]  (slot = px*8 + (c4 ^ (px>>2 & 7)), 2-way max)
//   phase 2: lanes 0-7 = 8 channel groups of ONE pixel; each RED.v4
//            target is one aligned 128B half-row = 1 cache line.
// Counts accumulated only by the cbase==0 half.
// -------------------------------------------------------------------------
__global__ void __launch_bounds__(256) accum_kernel(
    const float* __restrict__ x, const int* __restrict__ sp, int cbase) {
    __shared__ float4 s_t[A_PX * 8];      // 16 KB, swizzled [px][c4]
    __shared__ int    s_seg[A_PX];

    int t  = threadIdx.x;
    int p0 = blockIdx.x * A_PX;

    if (t < A_PX / 4) {
        int4 v = reinterpret_cast<const int4*>(sp + p0)[t];
        s_seg[t * 4 + 0] = v.x;
        s_seg[t * 4 + 1] = v.y;
        s_seg[t * 4 + 2] = v.z;
        s_seg[t * 4 + 3] = v.w;
    }

    float* s_f = reinterpret_cast<float*>(s_t);
#pragma unroll
    for (int i = 0; i < 4; i++) {
        int idx = i * 256 + t;            // 0..1023
        int c   = idx >> 5;               // local channel 0..31
        int f   = idx & 31;               // float4 column 0..31
        float4 v = __ldcs(reinterpret_cast<const float4*>(
            x + (size_t)(cbase + c) * NPIX + p0 + f * 4));
        int c4 = c >> 2, comp = c & 3;
#pragma unroll
        for (int k = 0; k < 4; k++) {
            int px   = f * 4 + k;
            int slot = px * 8 + (c4 ^ (f & 7));   // f == px>>2
            s_f[slot * 4 + comp] = (&v.x)[k];
        }
    }
    __syncthreads();

    if (cbase == 0 && t < A_PX) atomicAdd(&g_cnt[s_seg[t]], 1.0f);

#pragma unroll
    for (int r = 0; r < 4; r++) {
        int pair = r * 256 + t;           // 0..1023
        int px   = pair >> 3;             // lanes 0-7 same px
        int cg   = pair & 7;
        int seg  = s_seg[px];
        float4 v = s_t[px * 8 + (cg ^ ((px >> 2) & 7))];
        red_add_v4(&g_sums[(size_t)seg * CCH + cbase + cg * 4],
                   v.x, v.y, v.z, v.w);
    }
}

// -------------------------------------------------------------------------
// Kernel 3: gather half the channels (cg = cgbase + blockIdx.y, 8 cgs).
// Protected R3/R11 body: smem-staged means (division fused), streaming
// float4 stores. grid = (64 chunks, 8 cgs).
// -------------------------------------------------------------------------
__global__ void __launch_bounds__(256) gather_kernel(
    const int* __restrict__ sp, float* __restrict__ out, int cgbase) {
    __shared__ float4 s_means[NUM_SP];    // 32 KB

    int tid = threadIdx.x;
    int cg  = cgbase + blockIdx.y;
    int pixBase = blockIdx.x * PIX_PER_TILE;

#pragma unroll
    for (int i = 0; i < NUM_SP / 256; i++) {
        int s = i * 256 + tid;
        float4 sum = *reinterpret_cast<const float4*>(
            &g_sums[(size_t)s * CCH + cg * 4]);
        float inv = __frcp_rn(fmaxf(g_cnt[s], 1.0f));
        s_means[s] = make_float4(sum.x * inv, sum.y * inv,
                                 sum.z * inv, sum.w * inv);
    }
    __syncthreads();

#pragma unroll
    for (int q = 0; q < QITER; q++) {
        int p = pixBase + (q * 256 + tid) * 4;
        int4 s4 = *reinterpret_cast<const int4*>(sp + p);

        float4 a = s_means[s4.x];
        float4 b = s_means[s4.y];
        float4 c = s_means[s4.z];
        float4 d = s_means[s4.w];

        __stcs(reinterpret_cast<float4*>(out + (size_t)(cg * 4 + 0) * NPIX + p),
               make_float4(a.x, b.x, c.x, d.x));
        __stcs(reinterpret_cast<float4*>(out + (size_t)(cg * 4 + 1) * NPIX + p),
               make_float4(a.y, b.y, c.y, d.y));
        __stcs(reinterpret_cast<float4*>(out + (size_t)(cg * 4 + 2) * NPIX + p),
               make_float4(a.z, b.z, c.z, d.z));
        __stcs(reinterpret_cast<float4*>(out + (size_t)(cg * 4 + 3) * NPIX + p),
               make_float4(a.w, b.w, c.w, d.w));
    }
}

// -------------------------------------------------------------------------
// Host-side auxiliary objects (created ONCE at static init — host objects
// only, no device memory). Used to fork the captured graph into parallel
// branches: A0 -> { G0 || A1 } -> G1.
// -------------------------------------------------------------------------
namespace {
struct Aux {
    cudaStream_t s2 = nullptr;
    cudaEvent_t  evFork = nullptr, evJoin = nullptr;
    Aux() {
        cudaStreamCreateWithFlags(&s2, cudaStreamNonBlocking);
        cudaEventCreateWithFlags(&evFork, cudaEventDisableTiming);
        cudaEventCreateWithFlags(&evJoin, cudaEventDisableTiming);
    }
};
Aux g_aux;   // constructed before main() returns control to the harness
}

// -------------------------------------------------------------------------
// kernel_launch: graph-capturable with a capture FORK.
//   s0: zero -> A0 ->(evFork)          -> A1 ->(wait evJoin)-> G1
//   s2:              (wait evFork)-> G0 ->(evJoin)
// G0 (gather ch0-31, DRAM-write bound) runs concurrently with A1
// (accum ch32-63, L2-atomic bound). Disjoint data, different walls.
// -------------------------------------------------------------------------
extern "C" void kernel_launch(void* const* d_in, const int* in_sizes, int n_in,
                              void* d_out, int out_size) {
    const float* x  = (const float*)d_in[0];
    const int*   sp = (const int*)d_in[1];
    float*       out = (float*)d_out;

    const int threads = 256;
    const int zero_blocks = (NUM_SP * CCH / 4) / threads;   // 128
    cudaStream_t s0 = 0;

    zero_kernel<<<zero_blocks, threads, 0, s0>>>();
    accum_kernel<<<A_BLOCKS, threads, 0, s0>>>(x, sp, 0);        // A0: ch 0-31 + counts

    // Fork: G0 depends on A0
    cudaEventRecord(g_aux.evFork, s0);
    cudaStreamWaitEvent(g_aux.s2, g_aux.evFork, 0);
    gather_kernel<<<dim3(N_CHUNKS, 8), threads, 0, g_aux.s2>>>(sp, out, 0);  // G0: ch 0-31
    cudaEventRecord(g_aux.evJoin, g_aux.s2);

    // Parallel branch on s0: A1 overlaps G0
    accum_kernel<<<A_BLOCKS, threads, 0, s0>>>(x, sp, 32);       // A1: ch 32-63

    // Join, then final gather half
    cudaStreamWaitEvent(s0, g_aux.evJoin, 0);
    gather_kernel<<<dim3(N_CHUNKS, 8), threads, 0, s0>>>(sp, out, 8);        // G1: ch 32-63
}

// round 15
// speedup vs baseline: 1.0413x; 1.0020x over previous
#include <cuda_runtime.h>
#include <cstdint>

// Problem shape (fixed for this instance)
#define NUM_SP 2048
#define CCH    64
#define NPIX   (1024 * 1024)

// Accum half-kernel tile: 128 px x 32 ch per block (measured 40.6us/half)
#define A_PX   128
#define A_BLOCKS (NPIX / A_PX)             // 8192

// Gather tiling: 16384 px per (chunk, cg) tile; monolithic 16 cgs
#define QITER  16
#define PIX_PER_TILE (QITER * 256 * 4)     // 16384
#define N_CHUNKS (NPIX / PIX_PER_TILE)     // 64

// Scratch (allocation-free rule: __device__ globals)
__device__ float g_sums[NUM_SP * CCH];   // [S, C] row-major, 512 KB (L2-hot)
__device__ float g_cnt[NUM_SP];

// -------------------------------------------------------------------------
// Kernel 1: zero scratch (vectorized)
// -------------------------------------------------------------------------
__global__ void zero_kernel() {
    int i = blockIdx.x * blockDim.x + threadIdx.x;
    reinterpret_cast<float4*>(g_sums)[i] = make_float4(0.f, 0.f, 0.f, 0.f);
    if (i < NUM_SP / 4)
        reinterpret_cast<float4*>(g_cnt)[i] = make_float4(0.f, 0.f, 0.f, 0.f);
}

// -------------------------------------------------------------------------
// Vectorized fire-and-forget global reduction (no "memory" clobber).
// -------------------------------------------------------------------------
__device__ __forceinline__ void red_add_v4(float* addr, float a, float b,
                                           float c, float d) {
    asm volatile("red.global.add.v4.f32 [%0], {%1, %2, %3, %4};"
                 :: "l"(addr), "f"(a), "f"(b), "f"(c), "f"(d));
}

// -------------------------------------------------------------------------
// Kernel 2: accumulate channels [cbase, cbase+32) — measured 40.6us/half
// (vs 45us/half for the monolithic 64-ch kernel; the aligned 128B half-row
// = exactly 1 cache line per RED.v4 is the win).
//   phase 1: coalesced streaming LDG.128, scalar-STS into swizzled
//            s_t[px][c4]  (slot = px*8 + (c4 ^ (px>>2 & 7)), 2-way max)
//   phase 2: lanes 0-7 = 8 channel groups of ONE pixel.
// Counts accumulated only by the cbase==0 half.
// -------------------------------------------------------------------------
__global__ void __launch_bounds__(256) accum_kernel(
    const float* __restrict__ x, const int* __restrict__ sp, int cbase) {
    __shared__ float4 s_t[A_PX * 8];      // 16 KB, swizzled [px][c4]
    __shared__ int    s_seg[A_PX];

    int t  = threadIdx.x;
    int p0 = blockIdx.x * A_PX;

    if (t < A_PX / 4) {
        int4 v = reinterpret_cast<const int4*>(sp + p0)[t];
        s_seg[t * 4 + 0] = v.x;
        s_seg[t * 4 + 1] = v.y;
        s_seg[t * 4 + 2] = v.z;
        s_seg[t * 4 + 3] = v.w;
    }

    float* s_f = reinterpret_cast<float*>(s_t);
#pragma unroll
    for (int i = 0; i < 4; i++) {
        int idx = i * 256 + t;            // 0..1023
        int c   = idx >> 5;               // local channel 0..31
        int f   = idx & 31;               // float4 column 0..31
        float4 v = __ldcs(reinterpret_cast<const float4*>(
            x + (size_t)(cbase + c) * NPIX + p0 + f * 4));
        int c4 = c >> 2, comp = c & 3;
#pragma unroll
        for (int k = 0; k < 4; k++) {
            int px   = f * 4 + k;
            int slot = px * 8 + (c4 ^ (f & 7));   // f == px>>2
            s_f[slot * 4 + comp] = (&v.x)[k];
        }
    }
    __syncthreads();

    if (cbase == 0 && t < A_PX) atomicAdd(&g_cnt[s_seg[t]], 1.0f);

#pragma unroll
    for (int r = 0; r < 4; r++) {
        int pair = r * 256 + t;           // 0..1023
        int px   = pair >> 3;             // lanes 0-7 same px
        int cg   = pair & 7;
        int seg  = s_seg[px];
        float4 v = s_t[px * 8 + (cg ^ ((px >> 2) & 7))];
        red_add_v4(&g_sums[(size_t)seg * CCH + cbase + cg * 4],
                   v.x, v.y, v.z, v.w);
    }
}

// -------------------------------------------------------------------------
// Kernel 3: gather/broadcast — monolithic (all 16 cgs; measured faster
// than split halves), smem-staged means, streaming stores.
// __launch_bounds__(256, 6): cap regs (~42) so 6 blocks/SM co-reside
// (was 4 at 58 regs) -> more stores in flight -> higher write BW.
// -------------------------------------------------------------------------
__global__ void __launch_bounds__(256, 6) gather_kernel(
    const int* __restrict__ sp, float* __restrict__ out) {
    __shared__ float4 s_means[NUM_SP];    // 32 KB

    int tid = threadIdx.x;
    int cg  = blockIdx.y;                 // 0..15
    int pixBase = blockIdx.x * PIX_PER_TILE;

#pragma unroll
    for (int i = 0; i < NUM_SP / 256; i++) {
        int s = i * 256 + tid;
        float4 sum = *reinterpret_cast<const float4*>(
            &g_sums[(size_t)s * CCH + cg * 4]);
        float inv = __frcp_rn(fmaxf(g_cnt[s], 1.0f));
        s_means[s] = make_float4(sum.x * inv, sum.y * inv,
                                 sum.z * inv, sum.w * inv);
    }
    __syncthreads();

#pragma unroll
    for (int q = 0; q < QITER; q++) {
        int p = pixBase + (q * 256 + tid) * 4;
        int4 s4 = *reinterpret_cast<const int4*>(sp + p);

        float4 a = s_means[s4.x];
        float4 b = s_means[s4.y];
        float4 c = s_means[s4.z];
        float4 d = s_means[s4.w];

        __stcs(reinterpret_cast<float4*>(out + (size_t)(cg * 4 + 0) * NPIX + p),
               make_float4(a.x, b.x, c.x, d.x));
        __stcs(reinterpret_cast<float4*>(out + (size_t)(cg * 4 + 1) * NPIX + p),
               make_float4(a.y, b.y, c.y, d.y));
        __stcs(reinterpret_cast<float4*>(out + (size_t)(cg * 4 + 2) * NPIX + p),
               make_float4(a.z, b.z, c.z, d.z));
        __stcs(reinterpret_cast<float4*>(out + (size_t)(cg * 4 + 3) * NPIX + p),
               make_float4(a.w, b.w, c.w, d.w));
    }
}

// -------------------------------------------------------------------------
// kernel_launch: graph-capturable, PLAIN SERIAL (all overlap mechanisms
// measured ineffective in this harness). Order: zero, A0, A1, G.
// ncu capture slot #4 = gather_kernel.
// -------------------------------------------------------------------------
extern "C" void kernel_launch(void* const* d_in, const int* in_sizes, int n_in,
                              void* d_out, int out_size) {
    const float* x  = (const float*)d_in[0];
    const int*   sp = (const int*)d_in[1];
    float*       out = (float*)d_out;

    const int threads = 256;
    const int zero_blocks = (NUM_SP * CCH / 4) / threads;   // 128

    zero_kernel<<<zero_blocks, threads>>>();
    accum_kernel<<<A_BLOCKS, threads>>>(x, sp, 0);    // ch 0-31 + counts
    accum_kernel<<<A_BLOCKS, threads>>>(x, sp, 32);   // ch 32-63
    gather_kernel<<<dim3(N_CHUNKS, 16), threads>>>(sp, out);
}

// round 16
// speedup vs baseline: 1.1086x; 1.0646x over previous
#include <cuda_runtime.h>
#include <cstdint>

// Problem shape (fixed for this instance)
#define NUM_SP 2048
#define CCH    64
#define NPIX   (1024 * 1024)

// Accum half-kernel tile: 128 px x 32 ch per block (measured 40.6us/half)
#define A_PX   128
#define A_BLOCKS (NPIX / A_PX)             // 8192

// Gather tiling: monolithic 16 cgs, 16384 px per (chunk, cg) tile
#define QITER  16
#define PIX_PER_TILE (QITER * 256 * 4)     // 16384
#define N_CHUNKS (NPIX / PIX_PER_TILE)     // 64

// Scratch (allocation-free rule: __device__ globals)
__device__ float g_sums[NUM_SP * CCH];   // [S, C] row-major, 512 KB (L2-hot)
__device__ float g_cnt[NUM_SP];

__device__ __forceinline__ void grid_dep_wait() {
    asm volatile("griddepcontrol.wait;" ::: "memory");
}

// -------------------------------------------------------------------------
// Kernel 1: zero scratch (vectorized)
// -------------------------------------------------------------------------
__global__ void zero_kernel() {
    int i = blockIdx.x * blockDim.x + threadIdx.x;
    reinterpret_cast<float4*>(g_sums)[i] = make_float4(0.f, 0.f, 0.f, 0.f);
    if (i < NUM_SP / 4)
        reinterpret_cast<float4*>(g_cnt)[i] = make_float4(0.f, 0.f, 0.f, 0.f);
}

// -------------------------------------------------------------------------
// Vectorized fire-and-forget global reduction (no "memory" clobber).
// -------------------------------------------------------------------------
__device__ __forceinline__ void red_add_v4(float* addr, float a, float b,
                                           float c, float d) {
    asm volatile("red.global.add.v4.f32 [%0], {%1, %2, %3, %4};"
                 :: "l"(addr), "f"(a), "f"(b), "f"(c), "f"(d));
}

// -------------------------------------------------------------------------
// Kernel 2: accumulate channels [cbase, cbase+32) — measured 40.6us/half.
// PDL: prologue (x LDG + smem transpose, no sums access) overlaps the
// predecessor's drain; grid_dep_wait() before any atomic guarantees
// (transitively) zero and the prior half are complete.
//   phase 1: coalesced streaming LDG.128, scalar-STS into swizzled
//            s_t[px][c4]  (slot = px*8 + (c4 ^ (px>>2 & 7)), 2-way max)
//   phase 2: lanes 0-7 = 8 channel groups of ONE pixel; each RED.v4
//            target = one aligned 128B half-row = exactly 1 cache line.
// Counts accumulated only by the cbase==0 half.
// -------------------------------------------------------------------------
__global__ void __launch_bounds__(256) accum_kernel(
    const float* __restrict__ x, const int* __restrict__ sp, int cbase) {
    __shared__ float4 s_t[A_PX * 8];      // 16 KB, swizzled [px][c4]
    __shared__ int    s_seg[A_PX];

    int t  = threadIdx.x;
    int p0 = blockIdx.x * A_PX;

    if (t < A_PX / 4) {
        int4 v = reinterpret_cast<const int4*>(sp + p0)[t];
        s_seg[t * 4 + 0] = v.x;
        s_seg[t * 4 + 1] = v.y;
        s_seg[t * 4 + 2] = v.z;
        s_seg[t * 4 + 3] = v.w;
    }

    float* s_f = reinterpret_cast<float*>(s_t);
#pragma unroll
    for (int i = 0; i < 4; i++) {
        int idx = i * 256 + t;            // 0..1023
        int c   = idx >> 5;               // local channel 0..31
        int f   = idx & 31;               // float4 column 0..31
        float4 v = __ldcs(reinterpret_cast<const float4*>(
            x + (size_t)(cbase + c) * NPIX + p0 + f * 4));
        int c4 = c >> 2, comp = c & 3;
#pragma unroll
        for (int k = 0; k < 4; k++) {
            int px   = f * 4 + k;
            int slot = px * 8 + (c4 ^ (f & 7));   // f == px>>2
            s_f[slot * 4 + comp] = (&v.x)[k];
        }
    }
    __syncthreads();

    grid_dep_wait();   // predecessor (zero / prior half) complete

    if (cbase == 0 && t < A_PX) atomicAdd(&g_cnt[s_seg[t]], 1.0f);

#pragma unroll
    for (int r = 0; r < 4; r++) {
        int pair = r * 256 + t;           // 0..1023
        int px   = pair >> 3;             // lanes 0-7 same px
        int cg   = pair & 7;
        int seg  = s_seg[px];
        float4 v = s_t[px * 8 + (cg ^ ((px >> 2) & 7))];
        red_add_v4(&g_sums[(size_t)seg * CCH + cbase + cg * 4],
                   v.x, v.y, v.z, v.w);
    }
}

// -------------------------------------------------------------------------
// Kernel 3: gather/broadcast — EXACT R11 body (measured 49.6us; 58 regs,
// NO min-blocks clamp — the R15 reg-cap regressed it to 64us).
// Monolithic 16 cgs, smem-staged means (division fused), streaming stores.
// PDL wait before staging (sums must be final).
// -------------------------------------------------------------------------
__global__ void __launch_bounds__(256) gather_kernel(
    const int* __restrict__ sp, float* __restrict__ out) {
    __shared__ float4 s_means[NUM_SP];    // 32 KB

    int tid = threadIdx.x;
    int cg  = blockIdx.y;                 // 0..15
    int pixBase = blockIdx.x * PIX_PER_TILE;

    grid_dep_wait();   // A1 complete (transitively A0, zero)

#pragma unroll
    for (int i = 0; i < NUM_SP / 256; i++) {
        int s = i * 256 + tid;
        float4 sum = *reinterpret_cast<const float4*>(
            &g_sums[(size_t)s * CCH + cg * 4]);
        float inv = __frcp_rn(fmaxf(g_cnt[s], 1.0f));
        s_means[s] = make_float4(sum.x * inv, sum.y * inv,
                                 sum.z * inv, sum.w * inv);
    }
    __syncthreads();

#pragma unroll
    for (int q = 0; q < QITER; q++) {
        int p = pixBase + (q * 256 + tid) * 4;
        int4 s4 = *reinterpret_cast<const int4*>(sp + p);

        float4 a = s_means[s4.x];
        float4 b = s_means[s4.y];
        float4 c = s_means[s4.z];
        float4 d = s_means[s4.w];

        __stcs(reinterpret_cast<float4*>(out + (size_t)(cg * 4 + 0) * NPIX + p),
               make_float4(a.x, b.x, c.x, d.x));
        __stcs(reinterpret_cast<float4*>(out + (size_t)(cg * 4 + 1) * NPIX + p),
               make_float4(a.y, b.y, c.y, d.y));
        __stcs(reinterpret_cast<float4*>(out + (size_t)(cg * 4 + 2) * NPIX + p),
               make_float4(a.z, b.z, c.z, d.z));
        __stcs(reinterpret_cast<float4*>(out + (size_t)(cg * 4 + 3) * NPIX + p),
               make_float4(a.w, b.w, c.w, d.w));
    }
}

// -------------------------------------------------------------------------
// kernel_launch: graph-capturable, single stream, PDL prologue-overlap on
// A0, A1, gather (the mechanism that measurably helped in R10/R11).
// Order: zero, A0, A1, G.   ncu capture slot #4 = A1.
// -------------------------------------------------------------------------
extern "C" void kernel_launch(void* const* d_in, const int* in_sizes, int n_in,
                              void* d_out, int out_size) {
    const float* x  = (const float*)d_in[0];
    const int*   sp = (const int*)d_in[1];
    float*       out = (float*)d_out;

    const int threads = 256;
    const int zero_blocks = (NUM_SP * CCH / 4) / threads;   // 128

    zero_kernel<<<zero_blocks, threads>>>();

    cudaLaunchAttribute pdl[1];
    pdl[0].id = cudaLaunchAttributeProgrammaticStreamSerialization;
    pdl[0].val.programmaticStreamSerializationAllowed = 1;

    {   // A0: ch 0-31 + counts (prologue overlaps zero's drain)
        cudaLaunchConfig_t cfg = {};
        cfg.gridDim  = dim3(A_BLOCKS);
        cfg.blockDim = dim3(threads);
        cfg.stream   = 0;
        cfg.attrs    = pdl;
        cfg.numAttrs = 1;
        cudaLaunchKernelEx(&cfg, accum_kernel, x, sp, 0);
    }
    {   // A1: ch 32-63 (prologue overlaps A0's drain)
        cudaLaunchConfig_t cfg = {};
        cfg.gridDim  = dim3(A_BLOCKS);
        cfg.blockDim = dim3(threads);
        cfg.stream   = 0;
        cfg.attrs    = pdl;
        cfg.numAttrs = 1;
        cudaLaunchKernelEx(&cfg, accum_kernel, x, sp, 32);
    }
    {   // G: monolithic gather (prologue overlaps A1's drain)
        cudaLaunchConfig_t cfg = {};
        cfg.gridDim  = dim3(N_CHUNKS, 16);
        cfg.blockDim = dim3(threads);
        cfg.stream   = 0;
        cfg.attrs    = pdl;
        cfg.numAttrs = 1;
        cudaLaunchKernelEx(&cfg, gather_kernel, sp, out);
    }
}

// round 17
// speedup vs baseline: 1.1273x; 1.0169x over previous
#include <cuda_runtime.h>
#include <cstdint>

// Problem shape (fixed for this instance)
#define NUM_SP 2048
#define CCH    64
#define NPIX   (1024 * 1024)

// Accum tile: 128 px x 32 ch per block; blockIdx.y picks the channel half.
#define A_PX   128
#define A_BLOCKS_X (NPIX / A_PX)           // 8192

// Gather tiling: monolithic 16 cgs, 16384 px per (chunk, cg) tile
#define QITER  16
#define PIX_PER_TILE (QITER * 256 * 4)     // 16384
#define N_CHUNKS (NPIX / PIX_PER_TILE)     // 64

// Scratch (allocation-free rule: __device__ globals)
__device__ float g_sums[NUM_SP * CCH];   // [S, C] row-major, 512 KB (L2-hot)
__device__ float g_cnt[NUM_SP];

__device__ __forceinline__ void grid_dep_wait() {
    asm volatile("griddepcontrol.wait;" ::: "memory");
}

// -------------------------------------------------------------------------
// Kernel 1: zero scratch (vectorized)
// -------------------------------------------------------------------------
__global__ void zero_kernel() {
    int i = blockIdx.x * blockDim.x + threadIdx.x;
    reinterpret_cast<float4*>(g_sums)[i] = make_float4(0.f, 0.f, 0.f, 0.f);
    if (i < NUM_SP / 4)
        reinterpret_cast<float4*>(g_cnt)[i] = make_float4(0.f, 0.f, 0.f, 0.f);
}

// Profiling alignment shim: order noop, zero, accum, gather -> slot #4 = accum.
__global__ void noop_kernel() {}

// -------------------------------------------------------------------------
// Vectorized fire-and-forget global reduction (no "memory" clobber).
// -------------------------------------------------------------------------
__device__ __forceinline__ void red_add_v4(float* addr, float a, float b,
                                           float c, float d) {
    asm volatile("red.global.add.v4.f32 [%0], {%1, %2, %3, %4};"
                 :: "l"(addr), "f"(a), "f"(b), "f"(c), "f"(d));
}

// -------------------------------------------------------------------------
// Kernel 2: accumulate sums + counts, SINGLE LAUNCH, split-half grid.
// grid = (8192, 2): blockIdx.y = channel half (cbase = 32*y).
// Per-block body = the ncu-measured 40.6us/half structure (R12/R14):
//   phase 1: coalesced streaming LDG.128, scalar-STS into swizzled
//            s_t[px][c4]  (slot = px*8 + (c4 ^ (px>>2 & 7)), 2-way max)
//   phase 2: lanes 0-7 = 8 channel groups of ONE pixel; each RED.v4
//            target = one aligned 128B half-row = exactly 1 cache line.
// Counts accumulated only by the y==0 half.
// PDL: prologue (x LDG + transpose, no sums access) overlaps zero's drain;
// grid_dep_wait() before atomics guarantees zero completed.
// -------------------------------------------------------------------------
__global__ void __launch_bounds__(256) accum_kernel(
    const float* __restrict__ x, const int* __restrict__ sp) {
    __shared__ float4 s_t[A_PX * 8];      // 16 KB, swizzled [px][c4]
    __shared__ int    s_seg[A_PX];

    int t     = threadIdx.x;
    int cbase = blockIdx.y * 32;
    int p0    = blockIdx.x * A_PX;

    if (t < A_PX / 4) {
        int4 v = reinterpret_cast<const int4*>(sp + p0)[t];
        s_seg[t * 4 + 0] = v.x;
        s_seg[t * 4 + 1] = v.y;
        s_seg[t * 4 + 2] = v.z;
        s_seg[t * 4 + 3] = v.w;
    }

    float* s_f = reinterpret_cast<float*>(s_t);
#pragma unroll
    for (int i = 0; i < 4; i++) {
        int idx = i * 256 + t;            // 0..1023
        int c   = idx >> 5;               // local channel 0..31
        int f   = idx & 31;               // float4 column 0..31
        float4 v = __ldcs(reinterpret_cast<const float4*>(
            x + (size_t)(cbase + c) * NPIX + p0 + f * 4));
        int c4 = c >> 2, comp = c & 3;
#pragma unroll
        for (int k = 0; k < 4; k++) {
            int px   = f * 4 + k;
            int slot = px * 8 + (c4 ^ (f & 7));   // f == px>>2
            s_f[slot * 4 + comp] = (&v.x)[k];
        }
    }
    __syncthreads();

    grid_dep_wait();   // zero_kernel complete before any atomic

    if (blockIdx.y == 0 && t < A_PX) atomicAdd(&g_cnt[s_seg[t]], 1.0f);

#pragma unroll
    for (int r = 0; r < 4; r++) {
        int pair = r * 256 + t;           // 0..1023
        int px   = pair >> 3;             // lanes 0-7 same px
        int cg   = pair & 7;
        int seg  = s_seg[px];
        float4 v = s_t[px * 8 + (cg ^ ((px >> 2) & 7))];
        red_add_v4(&g_sums[(size_t)seg * CCH + cbase + cg * 4],
                   v.x, v.y, v.z, v.w);
    }
}

// -------------------------------------------------------------------------
// Kernel 3: gather/broadcast — EXACT R11 body (measured 49.6us, 58 regs,
// no min-blocks clamp). Monolithic 16 cgs, smem-staged means (division
// fused), streaming stores. PDL wait before staging.
// -------------------------------------------------------------------------
__global__ void __launch_bounds__(256) gather_kernel(
    const int* __restrict__ sp, float* __restrict__ out) {
    __shared__ float4 s_means[NUM_SP];    // 32 KB

    int tid = threadIdx.x;
    int cg  = blockIdx.y;                 // 0..15
    int pixBase = blockIdx.x * PIX_PER_TILE;

    grid_dep_wait();   // accum complete (transitively zero)

#pragma unroll
    for (int i = 0; i < NUM_SP / 256; i++) {
        int s = i * 256 + tid;
        float4 sum = *reinterpret_cast<const float4*>(
            &g_sums[(size_t)s * CCH + cg * 4]);
        float inv = __frcp_rn(fmaxf(g_cnt[s], 1.0f));
        s_means[s] = make_float4(sum.x * inv, sum.y * inv,
                                 sum.z * inv, sum.w * inv);
    }
    __syncthreads();

#pragma unroll
    for (int q = 0; q < QITER; q++) {
        int p = pixBase + (q * 256 + tid) * 4;
        int4 s4 = *reinterpret_cast<const int4*>(sp + p);

        float4 a = s_means[s4.x];
        float4 b = s_means[s4.y];
        float4 c = s_means[s4.z];
        float4 d = s_means[s4.w];

        __stcs(reinterpret_cast<float4*>(out + (size_t)(cg * 4 + 0) * NPIX + p),
               make_float4(a.x, b.x, c.x, d.x));
        __stcs(reinterpret_cast<float4*>(out + (size_t)(cg * 4 + 1) * NPIX + p),
               make_float4(a.y, b.y, c.y, d.y));
        __stcs(reinterpret_cast<float4*>(out + (size_t)(cg * 4 + 2) * NPIX + p),
               make_float4(a.z, b.z, c.z, d.z));
        __stcs(reinterpret_cast<float4*>(out + (size_t)(cg * 4 + 3) * NPIX + p),
               make_float4(a.w, b.w, c.w, d.w));
    }
}

// -------------------------------------------------------------------------
// kernel_launch: graph-capturable. EXACT R11 launch structure (the best
// measured config): noop, zero, accum[PDL], gather[PDL]. Only the accum
// grid changed to (8192, 2) with the split-half body.
// ncu capture slot #4 = accum_kernel.
// -------------------------------------------------------------------------
extern "C" void kernel_launch(void* const* d_in, const int* in_sizes, int n_in,
                              void* d_out, int out_size) {
    const float* x  = (const float*)d_in[0];
    const int*   sp = (const int*)d_in[1];
    float*       out = (float*)d_out;

    const int threads = 256;
    const int zero_blocks = (NUM_SP * CCH / 4) / threads;   // 128

    noop_kernel<<<1, 1>>>();
    zero_kernel<<<zero_blocks, threads>>>();

    cudaLaunchAttribute pdl[1];
    pdl[0].id = cudaLaunchAttributeProgrammaticStreamSerialization;
    pdl[0].val.programmaticStreamSerializationAllowed = 1;

    {   // accum: both halves in ONE launch, overlaps zero's drain
        cudaLaunchConfig_t cfg = {};
        cfg.gridDim  = dim3(A_BLOCKS_X, 2);
        cfg.blockDim = dim3(threads);
        cfg.stream   = 0;
        cfg.attrs    = pdl;
        cfg.numAttrs = 1;
        cudaLaunchKernelEx(&cfg, accum_kernel, x, sp);
    }
    {   // gather: overlaps accum's drain
        cudaLaunchConfig_t cfg = {};
        cfg.gridDim  = dim3(N_CHUNKS, 16);
        cfg.blockDim = dim3(threads);
        cfg.stream   = 0;
        cfg.attrs    = pdl;
        cfg.numAttrs = 1;
        cudaLaunchKernelEx(&cfg, gather_kernel, sp, out);
    }
}